// round 1
// baseline (speedup 1.0000x reference)
#include <cuda_runtime.h>
#include <cuda_bf16.h>
#include <math.h>

// ---------------- problem constants ----------------
#define S_LEN 128
#define BATCH 32
#define HID   1024
#define EMB   1024
#define VOCAB 32000
#define SB    (S_LEN * BATCH)          // 4096
#define BH    (BATCH * HID)            // 32768

// ---------------- scratch (device globals; no runtime alloc) ----------------
__device__ float g_embeds[SB * EMB];     // [S*B, E]
__device__ float g_xi1[SB * HID];
__device__ float g_xf1[SB * HID];
__device__ float g_xi2[SB * HID];
__device__ float g_xf2[SB * HID];
__device__ float g_lats1[SB * HID];      // layer-1 latent sequence (= l1_out)
__device__ float g_lats2[SB * HID];      // layer-2 latent sequence (= l2_out)
__device__ float g_part0[8 * BH];        // split-K partials, gate i: [kc][g*32+b]
__device__ float g_part1[8 * BH];        // split-K partials, gate f

// ---------------- embedding gather ----------------
__global__ void embed_gather(const int* __restrict__ word,
                             const float* __restrict__ emb,
                             float* __restrict__ out) {
    int row = blockIdx.x;                 // 0..4095 = s*B+b
    int w = word[row];
    const float4* src = (const float4*)(emb + (size_t)w * EMB);
    float4* dst = (float4*)(out + (size_t)row * EMB);
    dst[threadIdx.x] = src[threadIdx.x];  // 256 threads * float4 = 1024 floats
}

// ---------------- fp32 NT SGEMM with bias: C[M,N] = A[M,K] * B[N,K]^T + bias[N] ----
// BM=BN=128, BK=16, 256 threads, 8x8 per-thread tile. M%128==0, N%128==0, K%16==0.
__global__ __launch_bounds__(256, 2)
void sgemm_nt_bias(const float* __restrict__ A, const float* __restrict__ B,
                   const float* __restrict__ bias, float* __restrict__ C,
                   int M, int N, int K) {
    __shared__ float As[16][128];
    __shared__ float Bs[16][128];
    int tid = threadIdx.x;
    int bn = blockIdx.x * 128;
    int bm = blockIdx.y * 128;
    int tx = tid & 15;        // n-dim
    int ty = tid >> 4;        // m-dim
    int lr = tid >> 2;        // 0..63: load row
    int lc = (tid & 3) << 2;  // 0,4,8,12: load k-col

    float acc[8][8];
#pragma unroll
    for (int i = 0; i < 8; i++)
#pragma unroll
        for (int j = 0; j < 8; j++) acc[i][j] = 0.f;

    const float* Ap = A + (size_t)(bm + lr) * K + lc;
    const float* Bp = B + (size_t)(bn + lr) * K + lc;

    for (int k0 = 0; k0 < K; k0 += 16) {
        float4 a0 = *(const float4*)(Ap + k0);
        float4 a1 = *(const float4*)(Ap + (size_t)64 * K + k0);
        float4 b0 = *(const float4*)(Bp + k0);
        float4 b1 = *(const float4*)(Bp + (size_t)64 * K + k0);
        __syncthreads();
        As[lc + 0][lr] = a0.x; As[lc + 1][lr] = a0.y; As[lc + 2][lr] = a0.z; As[lc + 3][lr] = a0.w;
        As[lc + 0][64 + lr] = a1.x; As[lc + 1][64 + lr] = a1.y; As[lc + 2][64 + lr] = a1.z; As[lc + 3][64 + lr] = a1.w;
        Bs[lc + 0][lr] = b0.x; Bs[lc + 1][lr] = b0.y; Bs[lc + 2][lr] = b0.z; Bs[lc + 3][lr] = b0.w;
        Bs[lc + 0][64 + lr] = b1.x; Bs[lc + 1][64 + lr] = b1.y; Bs[lc + 2][64 + lr] = b1.z; Bs[lc + 3][64 + lr] = b1.w;
        __syncthreads();
#pragma unroll
        for (int k = 0; k < 16; k++) {
            float ra[8], rb[8];
            *(float4*)&ra[0] = *(const float4*)&As[k][ty * 4];
            *(float4*)&ra[4] = *(const float4*)&As[k][64 + ty * 4];
            *(float4*)&rb[0] = *(const float4*)&Bs[k][tx * 4];
            *(float4*)&rb[4] = *(const float4*)&Bs[k][64 + tx * 4];
#pragma unroll
            for (int i = 0; i < 8; i++)
#pragma unroll
                for (int j = 0; j < 8; j++) acc[i][j] += ra[i] * rb[j];
        }
    }

#pragma unroll
    for (int i = 0; i < 8; i++) {
        int m = bm + ((i < 4) ? (ty * 4 + i) : (64 + ty * 4 + i - 4));
        float* Crow = C + (size_t)m * N + bn;
#pragma unroll
        for (int jh = 0; jh < 2; jh++) {
            int nb = jh * 64 + tx * 4;
            float4 o;
            o.x = acc[i][jh * 4 + 0] + bias[bn + nb + 0];
            o.y = acc[i][jh * 4 + 1] + bias[bn + nb + 1];
            o.z = acc[i][jh * 4 + 2] + bias[bn + nb + 2];
            o.w = acc[i][jh * 4 + 3] + bias[bn + nb + 3];
            *(float4*)(Crow + nb) = o;
        }
    }
}

// ---------------- recurrence step, phase 1: split-K gate GEMM ----------------
// C_i[g,b] = sum_k Wi[g,k]*lat[b,k]   (and C_f with Wf), split over 8 K-chunks.
// grid = 256 blocks: gt = blk&31 (32 g's per gate), kc = blk>>5 (K-chunk of 128).
// 256 threads = 8 warps; warp w owns g = g0 + w*4 .. +3 for BOTH gates; lane = b.
__global__ __launch_bounds__(256)
void ran_step_gemm(const float* __restrict__ latp, const float* __restrict__ Wi,
                   const float* __restrict__ Wf,
                   float* __restrict__ part0, float* __restrict__ part1) {
    __shared__ float sLat[128][32];     // [k][b]  16KB
    __shared__ float sW[2][32][128];    // [gate][g][k]  32KB
    int tid = threadIdx.x;
    int gt = blockIdx.x & 31;
    int kc = blockIdx.x >> 5;
    int g0 = gt * 32;
    int k0 = kc * 128;

    // stage lat tile [32 b][128 k] -> sLat[k][b]
    for (int i = tid; i < 1024; i += 256) {
        int b = i >> 5, kq = i & 31;
        float4 v = *(const float4*)(latp + b * HID + k0 + kq * 4);
        sLat[kq * 4 + 0][b] = v.x;
        sLat[kq * 4 + 1][b] = v.y;
        sLat[kq * 4 + 2][b] = v.z;
        sLat[kq * 4 + 3][b] = v.w;
    }
    // stage W tiles: 2 x [32 g][128 k]
    for (int i = tid; i < 2048; i += 256) {
        int mtx = i >> 10;
        int g = (i >> 5) & 31, kq = i & 31;
        const float* Wp = mtx ? Wf : Wi;
        float4 v = *(const float4*)(Wp + (size_t)(g0 + g) * HID + k0 + kq * 4);
        *(float4*)&sW[mtx][g][kq * 4] = v;
    }
    __syncthreads();

    int w = tid >> 5, lane = tid & 31;
    float ai[4] = {0.f, 0.f, 0.f, 0.f};
    float af[4] = {0.f, 0.f, 0.f, 0.f};
#pragma unroll 8
    for (int k = 0; k < 128; k++) {
        float lv = sLat[k][lane];
#pragma unroll
        for (int j = 0; j < 4; j++) {
            ai[j] += sW[0][w * 4 + j][k] * lv;
            af[j] += sW[1][w * 4 + j][k] * lv;
        }
    }
    int base = kc * BH + (g0 + w * 4) * 32 + lane;
#pragma unroll
    for (int j = 0; j < 4; j++) {
        part0[base + j * 32] = ai[j];
        part1[base + j * 32] = af[j];
    }
}

// ---------------- recurrence step, phase 2: reduce + sigmoid + state update ---
__global__ __launch_bounds__(256)
void ran_step_epilogue(const float* __restrict__ part0, const float* __restrict__ part1,
                       const float* __restrict__ xi, const float* __restrict__ xf,
                       const float* __restrict__ x, const float* __restrict__ latp,
                       float* __restrict__ lato,
                       float* __restrict__ igout, float* __restrict__ fgout) {
    int p = blockIdx.x * 256 + threadIdx.x;   // 0..32767 = g*32+b
    float ci = 0.f, cf = 0.f;
#pragma unroll
    for (int kc = 0; kc < 8; kc++) {
        ci += part0[kc * BH + p];
        cf += part1[kc * BH + p];
    }
    int g = p >> 5, b = p & 31;
    int idx = b * HID + g;
    float ig = 1.f / (1.f + expf(-(ci + xi[idx])));
    float fg = 1.f / (1.f + expf(-(cf + xf[idx])));
    float nl = ig * x[idx] + fg * latp[idx];
    lato[idx] = nl;
    if (igout) {
        igout[idx] = ig;
        fgout[idx] = fg;
    }
}

// ---------------- host orchestration ----------------
extern "C" void kernel_launch(void* const* d_in, const int* in_sizes, int n_in,
                              void* d_out, int out_size) {
    const int*   word    = (const int*)d_in[0];
    const float* latent0 = (const float*)d_in[1];
    const float* emb     = (const float*)d_in[2];
    const float* h2o_w   = (const float*)d_in[3];
    const float* h2o_b   = (const float*)d_in[4];
    const float* Whi     = (const float*)d_in[5];
    const float* Wxi_w   = (const float*)d_in[6];
    const float* Wxi_b   = (const float*)d_in[7];
    const float* Whf     = (const float*)d_in[8];
    const float* Wxf_w   = (const float*)d_in[9];
    const float* Wxf_b   = (const float*)d_in[10];
    const float* Whi2    = (const float*)d_in[11];
    const float* Wxi2_w  = (const float*)d_in[12];
    const float* Wxi2_b  = (const float*)d_in[13];
    const float* Whf2    = (const float*)d_in[14];
    const float* Wxf2_w  = (const float*)d_in[15];
    const float* Wxf2_b  = (const float*)d_in[16];
    float* out = (float*)d_out;

    float *embeds, *xi1, *xf1, *xi2, *xf2, *lats1, *lats2, *p0, *p1;
    cudaGetSymbolAddress((void**)&embeds, g_embeds);
    cudaGetSymbolAddress((void**)&xi1, g_xi1);
    cudaGetSymbolAddress((void**)&xf1, g_xf1);
    cudaGetSymbolAddress((void**)&xi2, g_xi2);
    cudaGetSymbolAddress((void**)&xf2, g_xf2);
    cudaGetSymbolAddress((void**)&lats1, g_lats1);
    cudaGetSymbolAddress((void**)&lats2, g_lats2);
    cudaGetSymbolAddress((void**)&p0, g_part0);
    cudaGetSymbolAddress((void**)&p1, g_part1);

    // output layout (reference return order): latent | logits | ig_last | fg_last
    float* out_latent = out;
    float* out_logits = out + BH;
    float* out_ig     = out + (size_t)BH + (size_t)SB * VOCAB;
    float* out_fg     = out_ig + BH;

    // 1) embedding gather
    embed_gather<<<SB, 256>>>(word, emb, embeds);

    // 2) layer-1 input gate pre-activations
    {
        dim3 grid(HID / 128, SB / 128);
        sgemm_nt_bias<<<grid, 256>>>(embeds, Wxi_w, Wxi_b, xi1, SB, HID, EMB);
        sgemm_nt_bias<<<grid, 256>>>(embeds, Wxf_w, Wxf_b, xf1, SB, HID, EMB);
    }

    // 3) layer-1 recurrence
    for (int s = 0; s < S_LEN; s++) {
        const float* latp = (s == 0) ? latent0 : (lats1 + (size_t)(s - 1) * BH);
        ran_step_gemm<<<256, 256>>>(latp, Whi, Whf, p0, p1);
        ran_step_epilogue<<<128, 256>>>(p0, p1,
                                        xi1 + (size_t)s * BH, xf1 + (size_t)s * BH,
                                        embeds + (size_t)s * BH, latp,
                                        lats1 + (size_t)s * BH, nullptr, nullptr);
    }

    // 4) layer-2 input gate pre-activations (input = l1_out = lats1)
    {
        dim3 grid(HID / 128, SB / 128);
        sgemm_nt_bias<<<grid, 256>>>(lats1, Wxi2_w, Wxi2_b, xi2, SB, HID, EMB);
        sgemm_nt_bias<<<grid, 256>>>(lats1, Wxf2_w, Wxf2_b, xf2, SB, HID, EMB);
    }

    // 5) layer-2 recurrence (initial latent = layer-1 final latent)
    for (int s = 0; s < S_LEN; s++) {
        const float* latp = (s == 0) ? (lats1 + (size_t)(S_LEN - 1) * BH)
                                     : (lats2 + (size_t)(s - 1) * BH);
        bool last = (s == S_LEN - 1);
        ran_step_gemm<<<256, 256>>>(latp, Whi2, Whf2, p0, p1);
        ran_step_epilogue<<<128, 256>>>(p0, p1,
                                        xi2 + (size_t)s * BH, xf2 + (size_t)s * BH,
                                        lats1 + (size_t)s * BH, latp,
                                        lats2 + (size_t)s * BH,
                                        last ? out_ig : nullptr,
                                        last ? out_fg : nullptr);
    }

    // 6) final latent copy
    cudaMemcpyAsync(out_latent, lats2 + (size_t)(S_LEN - 1) * BH,
                    BH * sizeof(float), cudaMemcpyDeviceToDevice);

    // 7) logits = l2_out @ h2o_w^T + h2o_b
    {
        dim3 grid(VOCAB / 128, SB / 128);
        sgemm_nt_bias<<<grid, 256>>>(lats2, h2o_w, h2o_b, out_logits, SB, VOCAB, HID);
    }

    (void)in_sizes; (void)n_in; (void)out_size;
}

// round 2
// speedup vs baseline: 1.5063x; 1.5063x over previous
#include <cuda_runtime.h>
#include <cuda_bf16.h>
#include <math.h>
#include <stdint.h>

// ---------------- problem constants ----------------
#define S_LEN 128
#define BATCH 32
#define HID   1024
#define EMB   1024
#define VOCAB 32000
#define SB    (S_LEN * BATCH)          // 4096
#define BH    (BATCH * HID)            // 32768

// ---------------- scratch (device globals; no runtime alloc) ----------------
__device__ float g_embeds[SB * EMB];     // [S*B, E]
__device__ float g_xi1[SB * HID];
__device__ float g_xf1[SB * HID];
__device__ float g_xi2[SB * HID];
__device__ float g_xf2[SB * HID];
__device__ float g_lats1[SB * HID];      // layer-1 latent sequence (= l1_out)
__device__ float g_lats2[SB * HID];      // layer-2 latent sequence (= l2_out)
__device__ float g_part0[8 * BH];        // split-K partials, gate i: [kc][g*32+b]
__device__ float g_part1[8 * BH];        // split-K partials, gate f

// ---------------- embedding gather ----------------
__global__ void embed_gather(const int* __restrict__ word,
                             const float* __restrict__ emb,
                             float* __restrict__ out) {
    int row = blockIdx.x;                 // 0..4095 = s*B+b
    int w = word[row];
    const float4* src = (const float4*)(emb + (size_t)w * EMB);
    float4* dst = (float4*)(out + (size_t)row * EMB);
    dst[threadIdx.x] = src[threadIdx.x];  // 256 threads * float4 = 1024 floats
}

// ---------------- tf32 helpers ----------------
__device__ __forceinline__ uint32_t f2tf(float x) {
    uint32_t u;
    asm("cvt.rna.tf32.f32 %0, %1;" : "=r"(u) : "f"(x));
    return u;
}

__device__ __forceinline__ void mma_tf32(float c[4],
                                         uint32_t a0, uint32_t a1, uint32_t a2, uint32_t a3,
                                         uint32_t b0, uint32_t b1) {
    asm volatile(
        "mma.sync.aligned.m16n8k8.row.col.f32.tf32.tf32.f32 "
        "{%0,%1,%2,%3}, {%4,%5,%6,%7}, {%8,%9}, {%0,%1,%2,%3};"
        : "+f"(c[0]), "+f"(c[1]), "+f"(c[2]), "+f"(c[3])
        : "r"(a0), "r"(a1), "r"(a2), "r"(a3), "r"(b0), "r"(b1));
}

// ---------------- tf32 NT GEMM with bias: C[M,N] = A[M,K] * B[N,K]^T + bias[N] ----
// BM=BN=128, BK=16, 256 threads = 8 warps (4 m-tiles x 2 n-tiles), each warp
// computes 32x64 via m16n8k8 tf32 MMAs. M%128==0, N%128==0, K%16==0.
__global__ __launch_bounds__(256, 2)
void gemm_tf32_nt_bias(const float* __restrict__ A, const float* __restrict__ B,
                       const float* __restrict__ bias, float* __restrict__ C,
                       int M, int N, int K) {
    __shared__ uint32_t As[16][136];   // [k][m], pad 136 -> conflict-free frag loads
    __shared__ uint32_t Bs[16][136];   // [k][n]
    int tid = threadIdx.x;
    int bn = blockIdx.x * 128;
    int bm = blockIdx.y * 128;
    int wid = tid >> 5, lane = tid & 31;
    int wm = wid & 3;         // warp m-tile: rows wm*32 .. +31
    int wn = wid >> 2;        // warp n-tile: cols wn*64 .. +63
    int grp = lane >> 2;      // 0..7
    int tig = lane & 3;       // 0..3

    float acc[2][8][4];
#pragma unroll
    for (int i = 0; i < 2; i++)
#pragma unroll
        for (int j = 0; j < 8; j++)
#pragma unroll
            for (int q = 0; q < 4; q++) acc[i][j][q] = 0.f;

    int lr = tid >> 2;        // 0..63
    int lc = (tid & 3) << 2;  // 0,4,8,12
    const float* Ap = A + (size_t)(bm + lr) * K + lc;
    const float* Bp = B + (size_t)(bn + lr) * K + lc;

    for (int k0 = 0; k0 < K; k0 += 16) {
        float4 a0 = *(const float4*)(Ap + k0);
        float4 a1 = *(const float4*)(Ap + (size_t)64 * K + k0);
        float4 b0 = *(const float4*)(Bp + k0);
        float4 b1 = *(const float4*)(Bp + (size_t)64 * K + k0);
        __syncthreads();
        As[lc + 0][lr] = f2tf(a0.x); As[lc + 1][lr] = f2tf(a0.y);
        As[lc + 2][lr] = f2tf(a0.z); As[lc + 3][lr] = f2tf(a0.w);
        As[lc + 0][64 + lr] = f2tf(a1.x); As[lc + 1][64 + lr] = f2tf(a1.y);
        As[lc + 2][64 + lr] = f2tf(a1.z); As[lc + 3][64 + lr] = f2tf(a1.w);
        Bs[lc + 0][lr] = f2tf(b0.x); Bs[lc + 1][lr] = f2tf(b0.y);
        Bs[lc + 2][lr] = f2tf(b0.z); Bs[lc + 3][lr] = f2tf(b0.w);
        Bs[lc + 0][64 + lr] = f2tf(b1.x); Bs[lc + 1][64 + lr] = f2tf(b1.y);
        Bs[lc + 2][64 + lr] = f2tf(b1.z); Bs[lc + 3][64 + lr] = f2tf(b1.w);
        __syncthreads();

#pragma unroll
        for (int ks = 0; ks < 2; ks++) {
            int kk = ks * 8 + tig;   // kk and kk+4 are the two k-halves
            uint32_t af[2][4];
#pragma unroll
            for (int i = 0; i < 2; i++) {
                int mr = wm * 32 + i * 16 + grp;
                af[i][0] = As[kk][mr];
                af[i][1] = As[kk][mr + 8];
                af[i][2] = As[kk + 4][mr];
                af[i][3] = As[kk + 4][mr + 8];
            }
            uint32_t bf[8][2];
#pragma unroll
            for (int j = 0; j < 8; j++) {
                int nc = wn * 64 + j * 8 + grp;
                bf[j][0] = Bs[kk][nc];
                bf[j][1] = Bs[kk + 4][nc];
            }
#pragma unroll
            for (int i = 0; i < 2; i++)
#pragma unroll
                for (int j = 0; j < 8; j++)
                    mma_tf32(acc[i][j], af[i][0], af[i][1], af[i][2], af[i][3],
                             bf[j][0], bf[j][1]);
        }
    }

    // epilogue: c0/c1 -> (row, col..col+1), c2/c3 -> (row+8, col..col+1)
#pragma unroll
    for (int i = 0; i < 2; i++) {
        int row = bm + wm * 32 + i * 16 + grp;
#pragma unroll
        for (int j = 0; j < 8; j++) {
            int col = bn + wn * 64 + j * 8 + 2 * tig;
            float bsv0 = bias[col], bsv1 = bias[col + 1];
            float2 o0 = make_float2(acc[i][j][0] + bsv0, acc[i][j][1] + bsv1);
            float2 o1 = make_float2(acc[i][j][2] + bsv0, acc[i][j][3] + bsv1);
            *(float2*)(C + (size_t)row * N + col) = o0;
            *(float2*)(C + (size_t)(row + 8) * N + col) = o1;
        }
    }
}

// ---------------- recurrence step, phase 1: split-K gate GEMM ----------------
// C_i[g,b] = sum_k Wi[g,k]*lat[b,k]   (and C_f with Wf), split over 8 K-chunks.
// grid = 256 blocks: gt = blk&31 (32 g's per gate), kc = blk>>5 (K-chunk of 128).
// 256 threads = 8 warps; warp w owns g = g0 + w*4 .. +3 for BOTH gates; lane = b.
__global__ __launch_bounds__(256)
void ran_step_gemm(const float* __restrict__ latp, const float* __restrict__ Wi,
                   const float* __restrict__ Wf,
                   float* __restrict__ part0, float* __restrict__ part1) {
    __shared__ float sLat[128][32];     // [k][b]  16KB
    __shared__ float sW[2][32][128];    // [gate][g][k]  32KB
    int tid = threadIdx.x;
    int gt = blockIdx.x & 31;
    int kc = blockIdx.x >> 5;
    int g0 = gt * 32;
    int k0 = kc * 128;

    // stage lat tile [32 b][128 k] -> sLat[k][b]
    for (int i = tid; i < 1024; i += 256) {
        int b = i >> 5, kq = i & 31;
        float4 v = *(const float4*)(latp + b * HID + k0 + kq * 4);
        sLat[kq * 4 + 0][b] = v.x;
        sLat[kq * 4 + 1][b] = v.y;
        sLat[kq * 4 + 2][b] = v.z;
        sLat[kq * 4 + 3][b] = v.w;
    }
    // stage W tiles: 2 x [32 g][128 k]
    for (int i = tid; i < 2048; i += 256) {
        int mtx = i >> 10;
        int g = (i >> 5) & 31, kq = i & 31;
        const float* Wp = mtx ? Wf : Wi;
        float4 v = *(const float4*)(Wp + (size_t)(g0 + g) * HID + k0 + kq * 4);
        *(float4*)&sW[mtx][g][kq * 4] = v;
    }
    __syncthreads();

    int w = tid >> 5, lane = tid & 31;
    float ai[4] = {0.f, 0.f, 0.f, 0.f};
    float af[4] = {0.f, 0.f, 0.f, 0.f};
#pragma unroll 8
    for (int k = 0; k < 128; k++) {
        float lv = sLat[k][lane];
#pragma unroll
        for (int j = 0; j < 4; j++) {
            ai[j] += sW[0][w * 4 + j][k] * lv;
            af[j] += sW[1][w * 4 + j][k] * lv;
        }
    }
    int base = kc * BH + (g0 + w * 4) * 32 + lane;
#pragma unroll
    for (int j = 0; j < 4; j++) {
        part0[base + j * 32] = ai[j];
        part1[base + j * 32] = af[j];
    }
}

// ---------------- recurrence step, phase 2: reduce + sigmoid + state update ---
__global__ __launch_bounds__(256)
void ran_step_epilogue(const float* __restrict__ part0, const float* __restrict__ part1,
                       const float* __restrict__ xi, const float* __restrict__ xf,
                       const float* __restrict__ x, const float* __restrict__ latp,
                       float* __restrict__ lato,
                       float* __restrict__ igout, float* __restrict__ fgout) {
    int p = blockIdx.x * 256 + threadIdx.x;   // 0..32767 = g*32+b
    float ci = 0.f, cf = 0.f;
#pragma unroll
    for (int kc = 0; kc < 8; kc++) {
        ci += part0[kc * BH + p];
        cf += part1[kc * BH + p];
    }
    int g = p >> 5, b = p & 31;
    int idx = b * HID + g;
    float ig = 1.f / (1.f + expf(-(ci + xi[idx])));
    float fg = 1.f / (1.f + expf(-(cf + xf[idx])));
    float nl = ig * x[idx] + fg * latp[idx];
    lato[idx] = nl;
    if (igout) {
        igout[idx] = ig;
        fgout[idx] = fg;
    }
}

// ---------------- host orchestration ----------------
extern "C" void kernel_launch(void* const* d_in, const int* in_sizes, int n_in,
                              void* d_out, int out_size) {
    const int*   word    = (const int*)d_in[0];
    const float* latent0 = (const float*)d_in[1];
    const float* emb     = (const float*)d_in[2];
    const float* h2o_w   = (const float*)d_in[3];
    const float* h2o_b   = (const float*)d_in[4];
    const float* Whi     = (const float*)d_in[5];
    const float* Wxi_w   = (const float*)d_in[6];
    const float* Wxi_b   = (const float*)d_in[7];
    const float* Whf     = (const float*)d_in[8];
    const float* Wxf_w   = (const float*)d_in[9];
    const float* Wxf_b   = (const float*)d_in[10];
    const float* Whi2    = (const float*)d_in[11];
    const float* Wxi2_w  = (const float*)d_in[12];
    const float* Wxi2_b  = (const float*)d_in[13];
    const float* Whf2    = (const float*)d_in[14];
    const float* Wxf2_w  = (const float*)d_in[15];
    const float* Wxf2_b  = (const float*)d_in[16];
    float* out = (float*)d_out;

    float *embeds, *xi1, *xf1, *xi2, *xf2, *lats1, *lats2, *p0, *p1;
    cudaGetSymbolAddress((void**)&embeds, g_embeds);
    cudaGetSymbolAddress((void**)&xi1, g_xi1);
    cudaGetSymbolAddress((void**)&xf1, g_xf1);
    cudaGetSymbolAddress((void**)&xi2, g_xi2);
    cudaGetSymbolAddress((void**)&xf2, g_xf2);
    cudaGetSymbolAddress((void**)&lats1, g_lats1);
    cudaGetSymbolAddress((void**)&lats2, g_lats2);
    cudaGetSymbolAddress((void**)&p0, g_part0);
    cudaGetSymbolAddress((void**)&p1, g_part1);

    // output layout (reference return order): latent | logits | ig_last | fg_last
    float* out_latent = out;
    float* out_logits = out + BH;
    float* out_ig     = out + (size_t)BH + (size_t)SB * VOCAB;
    float* out_fg     = out_ig + BH;

    // 1) embedding gather
    embed_gather<<<SB, 256>>>(word, emb, embeds);

    // 2) layer-1 input gate pre-activations (tf32 tensor GEMM)
    {
        dim3 grid(HID / 128, SB / 128);
        gemm_tf32_nt_bias<<<grid, 256>>>(embeds, Wxi_w, Wxi_b, xi1, SB, HID, EMB);
        gemm_tf32_nt_bias<<<grid, 256>>>(embeds, Wxf_w, Wxf_b, xf1, SB, HID, EMB);
    }

    // 3) layer-1 recurrence (exact fp32)
    for (int s = 0; s < S_LEN; s++) {
        const float* latp = (s == 0) ? latent0 : (lats1 + (size_t)(s - 1) * BH);
        ran_step_gemm<<<256, 256>>>(latp, Whi, Whf, p0, p1);
        ran_step_epilogue<<<128, 256>>>(p0, p1,
                                        xi1 + (size_t)s * BH, xf1 + (size_t)s * BH,
                                        embeds + (size_t)s * BH, latp,
                                        lats1 + (size_t)s * BH, nullptr, nullptr);
    }

    // 4) layer-2 input gate pre-activations (input = l1_out = lats1)
    {
        dim3 grid(HID / 128, SB / 128);
        gemm_tf32_nt_bias<<<grid, 256>>>(lats1, Wxi2_w, Wxi2_b, xi2, SB, HID, EMB);
        gemm_tf32_nt_bias<<<grid, 256>>>(lats1, Wxf2_w, Wxf2_b, xf2, SB, HID, EMB);
    }

    // 5) layer-2 recurrence (initial latent = layer-1 final latent)
    for (int s = 0; s < S_LEN; s++) {
        const float* latp = (s == 0) ? (lats1 + (size_t)(S_LEN - 1) * BH)
                                     : (lats2 + (size_t)(s - 1) * BH);
        bool last = (s == S_LEN - 1);
        ran_step_gemm<<<256, 256>>>(latp, Whi2, Whf2, p0, p1);
        ran_step_epilogue<<<128, 256>>>(p0, p1,
                                        xi2 + (size_t)s * BH, xf2 + (size_t)s * BH,
                                        lats1 + (size_t)s * BH, latp,
                                        lats2 + (size_t)s * BH,
                                        last ? out_ig : nullptr,
                                        last ? out_fg : nullptr);
    }

    // 6) final latent copy
    cudaMemcpyAsync(out_latent, lats2 + (size_t)(S_LEN - 1) * BH,
                    BH * sizeof(float), cudaMemcpyDeviceToDevice);

    // 7) logits = l2_out @ h2o_w^T + h2o_b  (tf32 tensor GEMM)
    {
        dim3 grid(VOCAB / 128, SB / 128);
        gemm_tf32_nt_bias<<<grid, 256>>>(lats2, h2o_w, h2o_b, out_logits, SB, VOCAB, HID);
    }

    (void)in_sizes; (void)n_in; (void)out_size;
}

// round 3
// speedup vs baseline: 1.6539x; 1.0980x over previous
#include <cuda_runtime.h>
#include <cuda_bf16.h>
#include <math.h>
#include <stdint.h>

// ---------------- problem constants ----------------
#define S_LEN 128
#define BATCH 32
#define HID   1024
#define EMB   1024
#define VOCAB 32000
#define SB    (S_LEN * BATCH)          // 4096
#define BH    (BATCH * HID)            // 32768
#define NBLK  256                      // persistent recurrence grid

// ---------------- scratch (device globals; no runtime alloc) ----------------
__device__ float g_embeds[SB * EMB];     // [S*B, E]
__device__ float g_xi1[SB * HID];
__device__ float g_xf1[SB * HID];
__device__ float g_xi2[SB * HID];
__device__ float g_xf2[SB * HID];
__device__ float g_lats1[SB * HID];      // layer-1 latent sequence (= l1_out)
__device__ float g_lats2[SB * HID];      // layer-2 latent sequence (= l2_out)
__device__ float g_part0[8 * BH];        // split-K partials, gate i: [kc][g*32+b]
__device__ float g_part1[8 * BH];        // split-K partials, gate f
__device__ unsigned int g_bar_count;     // zero-init
__device__ unsigned int g_bar_gen;       // zero-init, monotonic across launches

// ---------------- embedding gather ----------------
__global__ void embed_gather(const int* __restrict__ word,
                             const float* __restrict__ emb,
                             float* __restrict__ out) {
    int row = blockIdx.x;                 // 0..4095 = s*B+b
    int w = word[row];
    const float4* src = (const float4*)(emb + (size_t)w * EMB);
    float4* dst = (float4*)(out + (size_t)row * EMB);
    dst[threadIdx.x] = src[threadIdx.x];  // 256 threads * float4 = 1024 floats
}

// ---------------- tf32 helpers ----------------
__device__ __forceinline__ uint32_t f2tf(float x) {
    uint32_t u;
    asm("cvt.rna.tf32.f32 %0, %1;" : "=r"(u) : "f"(x));
    return u;
}

__device__ __forceinline__ void mma_tf32(float c[4],
                                         uint32_t a0, uint32_t a1, uint32_t a2, uint32_t a3,
                                         uint32_t b0, uint32_t b1) {
    asm volatile(
        "mma.sync.aligned.m16n8k8.row.col.f32.tf32.tf32.f32 "
        "{%0,%1,%2,%3}, {%4,%5,%6,%7}, {%8,%9}, {%0,%1,%2,%3};"
        : "+f"(c[0]), "+f"(c[1]), "+f"(c[2]), "+f"(c[3])
        : "r"(a0), "r"(a1), "r"(a2), "r"(a3), "r"(b0), "r"(b1));
}

// ---------------- tf32 NT GEMM with bias: C[M,N] = A[M,K] * B[N,K]^T + bias[N] ----
__global__ __launch_bounds__(256, 2)
void gemm_tf32_nt_bias(const float* __restrict__ A, const float* __restrict__ B,
                       const float* __restrict__ bias, float* __restrict__ C,
                       int M, int N, int K) {
    __shared__ uint32_t As[16][136];   // [k][m]
    __shared__ uint32_t Bs[16][136];   // [k][n]
    int tid = threadIdx.x;
    int bn = blockIdx.x * 128;
    int bm = blockIdx.y * 128;
    int wid = tid >> 5, lane = tid & 31;
    int wm = wid & 3;
    int wn = wid >> 2;
    int grp = lane >> 2;
    int tig = lane & 3;

    float acc[2][8][4];
#pragma unroll
    for (int i = 0; i < 2; i++)
#pragma unroll
        for (int j = 0; j < 8; j++)
#pragma unroll
            for (int q = 0; q < 4; q++) acc[i][j][q] = 0.f;

    int lr = tid >> 2;
    int lc = (tid & 3) << 2;
    const float* Ap = A + (size_t)(bm + lr) * K + lc;
    const float* Bp = B + (size_t)(bn + lr) * K + lc;

    for (int k0 = 0; k0 < K; k0 += 16) {
        float4 a0 = *(const float4*)(Ap + k0);
        float4 a1 = *(const float4*)(Ap + (size_t)64 * K + k0);
        float4 b0 = *(const float4*)(Bp + k0);
        float4 b1 = *(const float4*)(Bp + (size_t)64 * K + k0);
        __syncthreads();
        As[lc + 0][lr] = f2tf(a0.x); As[lc + 1][lr] = f2tf(a0.y);
        As[lc + 2][lr] = f2tf(a0.z); As[lc + 3][lr] = f2tf(a0.w);
        As[lc + 0][64 + lr] = f2tf(a1.x); As[lc + 1][64 + lr] = f2tf(a1.y);
        As[lc + 2][64 + lr] = f2tf(a1.z); As[lc + 3][64 + lr] = f2tf(a1.w);
        Bs[lc + 0][lr] = f2tf(b0.x); Bs[lc + 1][lr] = f2tf(b0.y);
        Bs[lc + 2][lr] = f2tf(b0.z); Bs[lc + 3][lr] = f2tf(b0.w);
        Bs[lc + 0][64 + lr] = f2tf(b1.x); Bs[lc + 1][64 + lr] = f2tf(b1.y);
        Bs[lc + 2][64 + lr] = f2tf(b1.z); Bs[lc + 3][64 + lr] = f2tf(b1.w);
        __syncthreads();

#pragma unroll
        for (int ks = 0; ks < 2; ks++) {
            int kk = ks * 8 + tig;
            uint32_t af[2][4];
#pragma unroll
            for (int i = 0; i < 2; i++) {
                int mr = wm * 32 + i * 16 + grp;
                af[i][0] = As[kk][mr];
                af[i][1] = As[kk][mr + 8];
                af[i][2] = As[kk + 4][mr];
                af[i][3] = As[kk + 4][mr + 8];
            }
            uint32_t bf[8][2];
#pragma unroll
            for (int j = 0; j < 8; j++) {
                int nc = wn * 64 + j * 8 + grp;
                bf[j][0] = Bs[kk][nc];
                bf[j][1] = Bs[kk + 4][nc];
            }
#pragma unroll
            for (int i = 0; i < 2; i++)
#pragma unroll
                for (int j = 0; j < 8; j++)
                    mma_tf32(acc[i][j], af[i][0], af[i][1], af[i][2], af[i][3],
                             bf[j][0], bf[j][1]);
        }
    }

#pragma unroll
    for (int i = 0; i < 2; i++) {
        int row = bm + wm * 32 + i * 16 + grp;
#pragma unroll
        for (int j = 0; j < 8; j++) {
            int col = bn + wn * 64 + j * 8 + 2 * tig;
            float bsv0 = bias[col], bsv1 = bias[col + 1];
            float2 o0 = make_float2(acc[i][j][0] + bsv0, acc[i][j][1] + bsv1);
            float2 o1 = make_float2(acc[i][j][2] + bsv0, acc[i][j][3] + bsv1);
            *(float2*)(C + (size_t)row * N + col) = o0;
            *(float2*)(C + (size_t)(row + 8) * N + col) = o1;
        }
    }
}

// ---------------- software grid barrier (all NBLK blocks co-resident) --------
__device__ __forceinline__ void grid_barrier() {
    __syncthreads();
    if (threadIdx.x == 0) {
        volatile unsigned int* genp = &g_bar_gen;
        unsigned int gen = *genp;
        __threadfence();                        // release this block's writes
        unsigned int rank = atomicAdd(&g_bar_count, 1u);
        if (rank == NBLK - 1) {
            g_bar_count = 0u;
            __threadfence();
            *genp = gen + 1u;
        } else {
            while (*genp == gen) { __nanosleep(32); }
        }
        __threadfence();                        // acquire
    }
    __syncthreads();
}

// ---------------- persistent recurrence: one launch per layer ----------------
// Block blk: gt = blk&31 (32 gate rows per gate matrix), kc = blk>>5 (K-chunk).
// W tiles loaded into smem once; 128 steps with grid barriers between phases.
// dyn smem: sW[2][32][128] floats (32KB) + sLat[32][33] float4 (16.9KB)
__global__ __launch_bounds__(256)
void ran_recurrence(const float* __restrict__ Wi, const float* __restrict__ Wf,
                    const float* __restrict__ xi, const float* __restrict__ xf,
                    const float* __restrict__ xseq,   // [S][B][H] inputs
                    const float* __restrict__ lat0,   // initial latent [B][H]
                    float* __restrict__ lats,         // [S][B][H] outputs
                    float* __restrict__ part0, float* __restrict__ part1,
                    float* __restrict__ igout, float* __restrict__ fgout) {
    extern __shared__ char smem_raw[];
    float (*sW)[32][128] = (float (*)[32][128])smem_raw;              // [2][32][128]
    float4 (*sLat)[33] = (float4 (*)[33])(smem_raw + 2 * 32 * 128 * 4);

    int tid = threadIdx.x;
    int gt = blockIdx.x & 31;
    int kc = blockIdx.x >> 5;
    int g0 = gt * 32;
    int k0 = kc * 128;

    // ---- load W tiles once ----
    for (int i = tid; i < 2048; i += 256) {      // 2 gates x 32 g x 32 float4
        int mtx = i >> 10;
        int g = (i >> 5) & 31, kq = i & 31;
        const float* Wp = mtx ? Wf : Wi;
        *(float4*)&sW[mtx][g][kq * 4] =
            *(const float4*)(Wp + (size_t)(g0 + g) * HID + k0 + kq * 4);
    }

    int w = tid >> 5, lane = tid & 31;

    for (int s = 0; s < S_LEN; s++) {
        const float* latp = (s == 0) ? lat0 : (lats + (size_t)(s - 1) * BH);

        // ---- stage lat tile [32 b][128 k] (L2-coherent loads) ----
        for (int i = tid; i < 1024; i += 256) {
            int b = i >> 5, kq = i & 31;
            const float4* src = (const float4*)(latp + b * HID + k0 + kq * 4);
            sLat[b][kq] = __ldcg(src);
        }
        __syncthreads();

        // ---- split-K gate GEMM: 8 outputs per thread ----
        float ai[4] = {0.f, 0.f, 0.f, 0.f};
        float af[4] = {0.f, 0.f, 0.f, 0.f};
#pragma unroll 8
        for (int k4 = 0; k4 < 32; k4++) {
            float4 lv = sLat[lane][k4];
#pragma unroll
            for (int j = 0; j < 4; j++) {
                float4 wiv = *(const float4*)&sW[0][w * 4 + j][k4 * 4];
                float4 wfv = *(const float4*)&sW[1][w * 4 + j][k4 * 4];
                ai[j] += wiv.x * lv.x + wiv.y * lv.y + wiv.z * lv.z + wiv.w * lv.w;
                af[j] += wfv.x * lv.x + wfv.y * lv.y + wfv.z * lv.z + wfv.w * lv.w;
            }
        }
        int base = kc * BH + (g0 + w * 4) * 32 + lane;
#pragma unroll
        for (int j = 0; j < 4; j++) {
            part0[base + j * 32] = ai[j];
            part1[base + j * 32] = af[j];
        }

        grid_barrier();   // partials visible grid-wide

        // ---- epilogue: reduce + sigmoid + state update (128 outputs/block) ----
        if (tid < 128) {
            int p = blockIdx.x * 128 + tid;     // 0..32767 = g*32+b
            float ci = 0.f, cf = 0.f;
#pragma unroll
            for (int q = 0; q < 8; q++) {
                ci += __ldcg(&part0[q * BH + p]);
                cf += __ldcg(&part1[q * BH + p]);
            }
            int g = p >> 5, b = p & 31;
            int idx = b * HID + g;
            size_t sidx = (size_t)s * BH + idx;
            float ig = 1.f / (1.f + expf(-(ci + xi[sidx])));
            float fg = 1.f / (1.f + expf(-(cf + xf[sidx])));
            float nl = ig * xseq[sidx] + fg * __ldcg(latp + idx);
            lats[sidx] = nl;
            if (s == S_LEN - 1 && igout) {
                igout[idx] = ig;
                fgout[idx] = fg;
            }
        }

        if (s != S_LEN - 1) grid_barrier();   // lat[s] visible before next step
    }
}

// ---------------- host orchestration ----------------
extern "C" void kernel_launch(void* const* d_in, const int* in_sizes, int n_in,
                              void* d_out, int out_size) {
    const int*   word    = (const int*)d_in[0];
    const float* latent0 = (const float*)d_in[1];
    const float* emb     = (const float*)d_in[2];
    const float* h2o_w   = (const float*)d_in[3];
    const float* h2o_b   = (const float*)d_in[4];
    const float* Whi     = (const float*)d_in[5];
    const float* Wxi_w   = (const float*)d_in[6];
    const float* Wxi_b   = (const float*)d_in[7];
    const float* Whf     = (const float*)d_in[8];
    const float* Wxf_w   = (const float*)d_in[9];
    const float* Wxf_b   = (const float*)d_in[10];
    const float* Whi2    = (const float*)d_in[11];
    const float* Wxi2_w  = (const float*)d_in[12];
    const float* Wxi2_b  = (const float*)d_in[13];
    const float* Whf2    = (const float*)d_in[14];
    const float* Wxf2_w  = (const float*)d_in[15];
    const float* Wxf2_b  = (const float*)d_in[16];
    float* out = (float*)d_out;

    float *embeds, *xi1, *xf1, *xi2, *xf2, *lats1, *lats2, *p0, *p1;
    cudaGetSymbolAddress((void**)&embeds, g_embeds);
    cudaGetSymbolAddress((void**)&xi1, g_xi1);
    cudaGetSymbolAddress((void**)&xf1, g_xf1);
    cudaGetSymbolAddress((void**)&xi2, g_xi2);
    cudaGetSymbolAddress((void**)&xf2, g_xf2);
    cudaGetSymbolAddress((void**)&lats1, g_lats1);
    cudaGetSymbolAddress((void**)&lats2, g_lats2);
    cudaGetSymbolAddress((void**)&p0, g_part0);
    cudaGetSymbolAddress((void**)&p1, g_part1);

    const int SMEM_REC = 2 * 32 * 128 * 4 + 32 * 33 * 16;   // 49664 bytes
    static bool attr_done = false;
    if (!attr_done) {
        cudaFuncSetAttribute(ran_recurrence,
                             cudaFuncAttributeMaxDynamicSharedMemorySize, SMEM_REC);
        attr_done = true;
    }

    // output layout (reference return order): latent | logits | ig_last | fg_last
    float* out_latent = out;
    float* out_logits = out + BH;
    float* out_ig     = out + (size_t)BH + (size_t)SB * VOCAB;
    float* out_fg     = out_ig + BH;

    // 1) embedding gather
    embed_gather<<<SB, 256>>>(word, emb, embeds);

    // 2) layer-1 input gate pre-activations (tf32 tensor GEMM)
    {
        dim3 grid(HID / 128, SB / 128);
        gemm_tf32_nt_bias<<<grid, 256>>>(embeds, Wxi_w, Wxi_b, xi1, SB, HID, EMB);
        gemm_tf32_nt_bias<<<grid, 256>>>(embeds, Wxf_w, Wxf_b, xf1, SB, HID, EMB);
    }

    // 3) layer-1 recurrence (persistent, exact fp32)
    ran_recurrence<<<NBLK, 256, SMEM_REC>>>(Whi, Whf, xi1, xf1, embeds, latent0,
                                            lats1, p0, p1, nullptr, nullptr);

    // 4) layer-2 input gate pre-activations (input = l1_out = lats1)
    {
        dim3 grid(HID / 128, SB / 128);
        gemm_tf32_nt_bias<<<grid, 256>>>(lats1, Wxi2_w, Wxi2_b, xi2, SB, HID, EMB);
        gemm_tf32_nt_bias<<<grid, 256>>>(lats1, Wxf2_w, Wxf2_b, xf2, SB, HID, EMB);
    }

    // 5) layer-2 recurrence (initial latent = layer-1 final latent)
    ran_recurrence<<<NBLK, 256, SMEM_REC>>>(Whi2, Whf2, xi2, xf2, lats1,
                                            lats1 + (size_t)(S_LEN - 1) * BH,
                                            lats2, p0, p1, out_ig, out_fg);

    // 6) final latent copy
    cudaMemcpyAsync(out_latent, lats2 + (size_t)(S_LEN - 1) * BH,
                    BH * sizeof(float), cudaMemcpyDeviceToDevice);

    // 7) logits = l2_out @ h2o_w^T + h2o_b  (tf32 tensor GEMM)
    {
        dim3 grid(VOCAB / 128, SB / 128);
        gemm_tf32_nt_bias<<<grid, 256>>>(lats2, h2o_w, h2o_b, out_logits, SB, VOCAB, HID);
    }

    (void)in_sizes; (void)n_in; (void)out_size;
}

// round 4
// speedup vs baseline: 1.9356x; 1.1703x over previous
#include <cuda_runtime.h>
#include <cuda_bf16.h>
#include <math.h>
#include <stdint.h>

// ---------------- problem constants ----------------
#define S_LEN 128
#define BATCH 32
#define HID   1024
#define EMB   1024
#define VOCAB 32000
#define SB    (S_LEN * BATCH)          // 4096
#define BH    (BATCH * HID)            // 32768
#define NBLK  256                      // persistent recurrence grid

// ---------------- scratch (device globals; no runtime alloc) ----------------
__device__ float g_embeds[SB * EMB];      // [S*B, E] exact fp32
__device__ float g_embeds_tf[SB * EMB];   // tf32-rounded copy (GEMM A operand)
__device__ float g_xi1[SB * HID];
__device__ float g_xf1[SB * HID];
__device__ float g_xi2[SB * HID];
__device__ float g_xf2[SB * HID];
__device__ float g_lats1[SB * HID];       // layer-1 latent sequence (= l1_out)
__device__ float g_lats1_tf[SB * HID];
__device__ float g_lats2[SB * HID];       // layer-2 latent sequence (= l2_out)
__device__ float g_lats2_tf[SB * HID];
__device__ float g_part0[8 * BH];         // split-K partials, gate i
__device__ float g_part1[8 * BH];         // split-K partials, gate f
__device__ float g_h2o_tf[(size_t)VOCAB * HID];   // 131MB tf32 weight copy
__device__ float g_wx_tf[4][HID * EMB];           // tf32 copies of Wxi,Wxf,Wxi2,Wxf2
__device__ unsigned int g_bar_count;
__device__ unsigned int g_bar_gen;

// ---------------- tf32 helpers ----------------
__device__ __forceinline__ uint32_t f2tf(float x) {
    uint32_t u;
    asm("cvt.rna.tf32.f32 %0, %1;" : "=r"(u) : "f"(x));
    return u;
}

__device__ __forceinline__ void mma_tf32(float c[4],
                                         uint32_t a0, uint32_t a1, uint32_t a2, uint32_t a3,
                                         uint32_t b0, uint32_t b1) {
    asm volatile(
        "mma.sync.aligned.m16n8k8.row.col.f32.tf32.tf32.f32 "
        "{%0,%1,%2,%3}, {%4,%5,%6,%7}, {%8,%9}, {%0,%1,%2,%3};"
        : "+f"(c[0]), "+f"(c[1]), "+f"(c[2]), "+f"(c[3])
        : "r"(a0), "r"(a1), "r"(a2), "r"(a3), "r"(b0), "r"(b1));
}

__device__ __forceinline__ void cp_async16(void* smem_dst, const void* gsrc) {
    uint32_t s = (uint32_t)__cvta_generic_to_shared(smem_dst);
    asm volatile("cp.async.cg.shared.global [%0], [%1], 16;" :: "r"(s), "l"(gsrc));
}

// ---------------- tf32 rounding pre-pass ----------------
__global__ void to_tf32_kernel(const float* __restrict__ src, float* __restrict__ dst,
                               int n4) {
    int i = blockIdx.x * blockDim.x + threadIdx.x;
    if (i < n4) {
        float4 v = ((const float4*)src)[i];
        float4 o;
        o.x = __uint_as_float(f2tf(v.x));
        o.y = __uint_as_float(f2tf(v.y));
        o.z = __uint_as_float(f2tf(v.z));
        o.w = __uint_as_float(f2tf(v.w));
        ((float4*)dst)[i] = o;
    }
}

// ---------------- embedding gather (writes fp32 + tf32 copies) ----------------
__global__ void embed_gather(const int* __restrict__ word,
                             const float* __restrict__ emb,
                             float* __restrict__ out,
                             float* __restrict__ out_tf) {
    int row = blockIdx.x;                 // 0..4095 = s*B+b
    int w = word[row];
    float4 v = ((const float4*)(emb + (size_t)w * EMB))[threadIdx.x];
    ((float4*)(out + (size_t)row * EMB))[threadIdx.x] = v;
    float4 o;
    o.x = __uint_as_float(f2tf(v.x));
    o.y = __uint_as_float(f2tf(v.y));
    o.z = __uint_as_float(f2tf(v.z));
    o.w = __uint_as_float(f2tf(v.w));
    ((float4*)(out_tf + (size_t)row * EMB))[threadIdx.x] = o;
}

// ---------------- pipelined tf32 NT GEMM: C = A[M,K] * B[N,K]^T + bias[N] -----
// Inputs must be pre-rounded to tf32. BM=BN=128, BK=16, 3-stage cp.async.
// 256 threads = 8 warps (4 m x 2 n), warp tile 32x64 via m16n8k8.
#define PSTAGES 3
#define TSTRIDE 20                      // floats per tile row (16 data + 4 pad)
#define TILE_F  (128 * TSTRIDE)         // 2560 floats per tile
#define GEMM_SMEM (PSTAGES * 2 * TILE_F * 4)   // 61440 bytes

__global__ __launch_bounds__(256, 2)
void gemm_tf32_pipe(const float* __restrict__ A, const float* __restrict__ B,
                    const float* __restrict__ bias, float* __restrict__ C,
                    int M, int N, int K) {
    extern __shared__ float sm[];
    float* As = sm;                       // [PSTAGES][128][TSTRIDE]
    float* Bs = sm + PSTAGES * TILE_F;

    int tid = threadIdx.x;
    int bn = blockIdx.x * 128;
    int bm = blockIdx.y * 128;
    int wid = tid >> 5, lane = tid & 31;
    int wm = wid & 3;          // warp m-tile
    int wn = wid >> 2;         // warp n-tile
    int grp = lane >> 2;       // 0..7
    int tig = lane & 3;        // 0..3

    // load mapping: 512 16B-chunks per operand tile; thread does chunks tid, tid+256
    int r0 = tid >> 2, c0 = (tid & 3) << 2;          // chunk tid
    int r1 = (tid + 256) >> 2, c1 = c0;              // chunk tid+256 (same c)
    const float* Ab = A + (size_t)bm * K;
    const float* Bb = B + (size_t)bn * K;

    float acc[2][8][4];
#pragma unroll
    for (int i = 0; i < 2; i++)
#pragma unroll
        for (int j = 0; j < 8; j++)
#pragma unroll
            for (int q = 0; q < 4; q++) acc[i][j][q] = 0.f;

    int KT = K >> 4;

    // prologue: issue stages 0..PSTAGES-2
#pragma unroll
    for (int s = 0; s < PSTAGES - 1; s++) {
        int k0 = s * 16;
        cp_async16(&As[s * TILE_F + r0 * TSTRIDE + c0], Ab + (size_t)r0 * K + k0 + c0);
        cp_async16(&As[s * TILE_F + r1 * TSTRIDE + c1], Ab + (size_t)r1 * K + k0 + c1);
        cp_async16(&Bs[s * TILE_F + r0 * TSTRIDE + c0], Bb + (size_t)r0 * K + k0 + c0);
        cp_async16(&Bs[s * TILE_F + r1 * TSTRIDE + c1], Bb + (size_t)r1 * K + k0 + c1);
        asm volatile("cp.async.commit_group;");
    }

    for (int kt = 0; kt < KT; kt++) {
        asm volatile("cp.async.wait_group %0;" :: "n"(PSTAGES - 2));
        __syncthreads();

        const float* Ast = &As[(kt % PSTAGES) * TILE_F];
        const float* Bst = &Bs[(kt % PSTAGES) * TILE_F];

#pragma unroll
        for (int ks = 0; ks < 2; ks++) {
            int kk = ks * 8 + tig;        // kk, kk+4 are the two k-halves
            uint32_t af[2][4];
#pragma unroll
            for (int i = 0; i < 2; i++) {
                int mr = wm * 32 + i * 16 + grp;
                af[i][0] = __float_as_uint(Ast[mr * TSTRIDE + kk]);
                af[i][1] = __float_as_uint(Ast[(mr + 8) * TSTRIDE + kk]);
                af[i][2] = __float_as_uint(Ast[mr * TSTRIDE + kk + 4]);
                af[i][3] = __float_as_uint(Ast[(mr + 8) * TSTRIDE + kk + 4]);
            }
            uint32_t bf[8][2];
#pragma unroll
            for (int j = 0; j < 8; j++) {
                int nc = wn * 64 + j * 8 + grp;
                bf[j][0] = __float_as_uint(Bst[nc * TSTRIDE + kk]);
                bf[j][1] = __float_as_uint(Bst[nc * TSTRIDE + kk + 4]);
            }
#pragma unroll
            for (int i = 0; i < 2; i++)
#pragma unroll
                for (int j = 0; j < 8; j++)
                    mma_tf32(acc[i][j], af[i][0], af[i][1], af[i][2], af[i][3],
                             bf[j][0], bf[j][1]);
        }

        int nk = kt + PSTAGES - 1;
        if (nk < KT) {
            int st = nk % PSTAGES;
            int k0 = nk * 16;
            cp_async16(&As[st * TILE_F + r0 * TSTRIDE + c0], Ab + (size_t)r0 * K + k0 + c0);
            cp_async16(&As[st * TILE_F + r1 * TSTRIDE + c1], Ab + (size_t)r1 * K + k0 + c1);
            cp_async16(&Bs[st * TILE_F + r0 * TSTRIDE + c0], Bb + (size_t)r0 * K + k0 + c0);
            cp_async16(&Bs[st * TILE_F + r1 * TSTRIDE + c1], Bb + (size_t)r1 * K + k0 + c1);
        }
        asm volatile("cp.async.commit_group;");
    }

    // epilogue
#pragma unroll
    for (int i = 0; i < 2; i++) {
        int row = bm + wm * 32 + i * 16 + grp;
#pragma unroll
        for (int j = 0; j < 8; j++) {
            int col = bn + wn * 64 + j * 8 + 2 * tig;
            float bsv0 = bias[col], bsv1 = bias[col + 1];
            float2 o0 = make_float2(acc[i][j][0] + bsv0, acc[i][j][1] + bsv1);
            float2 o1 = make_float2(acc[i][j][2] + bsv0, acc[i][j][3] + bsv1);
            *(float2*)(C + (size_t)row * N + col) = o0;
            *(float2*)(C + (size_t)(row + 8) * N + col) = o1;
        }
    }
}

// ---------------- software grid barrier (all NBLK blocks co-resident) --------
__device__ __forceinline__ void grid_barrier() {
    __syncthreads();
    if (threadIdx.x == 0) {
        volatile unsigned int* genp = &g_bar_gen;
        unsigned int gen = *genp;
        __threadfence();
        unsigned int rank = atomicAdd(&g_bar_count, 1u);
        if (rank == NBLK - 1) {
            g_bar_count = 0u;
            __threadfence();
            *genp = gen + 1u;
        } else {
            while (*genp == gen) { __nanosleep(32); }
        }
        __threadfence();
    }
    __syncthreads();
}

// ---------------- persistent recurrence: one launch per layer ----------------
__global__ __launch_bounds__(256)
void ran_recurrence(const float* __restrict__ Wi, const float* __restrict__ Wf,
                    const float* __restrict__ xi, const float* __restrict__ xf,
                    const float* __restrict__ xseq,
                    const float* __restrict__ lat0,
                    float* __restrict__ lats,
                    float* __restrict__ lats_tf,      // tf32-rounded copy
                    float* __restrict__ part0, float* __restrict__ part1,
                    float* __restrict__ igout, float* __restrict__ fgout) {
    extern __shared__ char smem_raw[];
    float (*sW)[32][128] = (float (*)[32][128])smem_raw;
    float4 (*sLat)[33] = (float4 (*)[33])(smem_raw + 2 * 32 * 128 * 4);

    int tid = threadIdx.x;
    int gt = blockIdx.x & 31;
    int kc = blockIdx.x >> 5;
    int g0 = gt * 32;
    int k0 = kc * 128;

    for (int i = tid; i < 2048; i += 256) {
        int mtx = i >> 10;
        int g = (i >> 5) & 31, kq = i & 31;
        const float* Wp = mtx ? Wf : Wi;
        *(float4*)&sW[mtx][g][kq * 4] =
            *(const float4*)(Wp + (size_t)(g0 + g) * HID + k0 + kq * 4);
    }

    int w = tid >> 5, lane = tid & 31;

    for (int s = 0; s < S_LEN; s++) {
        const float* latp = (s == 0) ? lat0 : (lats + (size_t)(s - 1) * BH);

        for (int i = tid; i < 1024; i += 256) {
            int b = i >> 5, kq = i & 31;
            const float4* src = (const float4*)(latp + b * HID + k0 + kq * 4);
            sLat[b][kq] = __ldcg(src);
        }
        __syncthreads();

        float ai[4] = {0.f, 0.f, 0.f, 0.f};
        float af[4] = {0.f, 0.f, 0.f, 0.f};
#pragma unroll 8
        for (int k4 = 0; k4 < 32; k4++) {
            float4 lv = sLat[lane][k4];
#pragma unroll
            for (int j = 0; j < 4; j++) {
                float4 wiv = *(const float4*)&sW[0][w * 4 + j][k4 * 4];
                float4 wfv = *(const float4*)&sW[1][w * 4 + j][k4 * 4];
                ai[j] += wiv.x * lv.x + wiv.y * lv.y + wiv.z * lv.z + wiv.w * lv.w;
                af[j] += wfv.x * lv.x + wfv.y * lv.y + wfv.z * lv.z + wfv.w * lv.w;
            }
        }
        int base = kc * BH + (g0 + w * 4) * 32 + lane;
#pragma unroll
        for (int j = 0; j < 4; j++) {
            part0[base + j * 32] = ai[j];
            part1[base + j * 32] = af[j];
        }

        grid_barrier();

        if (tid < 128) {
            int p = blockIdx.x * 128 + tid;
            float ci = 0.f, cf = 0.f;
#pragma unroll
            for (int q = 0; q < 8; q++) {
                ci += __ldcg(&part0[q * BH + p]);
                cf += __ldcg(&part1[q * BH + p]);
            }
            int g = p >> 5, b = p & 31;
            int idx = b * HID + g;
            size_t sidx = (size_t)s * BH + idx;
            float ig = 1.f / (1.f + expf(-(ci + xi[sidx])));
            float fg = 1.f / (1.f + expf(-(cf + xf[sidx])));
            float nl = ig * xseq[sidx] + fg * __ldcg(latp + idx);
            lats[sidx] = nl;
            lats_tf[sidx] = __uint_as_float(f2tf(nl));
            if (s == S_LEN - 1 && igout) {
                igout[idx] = ig;
                fgout[idx] = fg;
            }
        }

        if (s != S_LEN - 1) grid_barrier();
    }
}

// ---------------- host orchestration ----------------
extern "C" void kernel_launch(void* const* d_in, const int* in_sizes, int n_in,
                              void* d_out, int out_size) {
    const int*   word    = (const int*)d_in[0];
    const float* latent0 = (const float*)d_in[1];
    const float* emb     = (const float*)d_in[2];
    const float* h2o_w   = (const float*)d_in[3];
    const float* h2o_b   = (const float*)d_in[4];
    const float* Whi     = (const float*)d_in[5];
    const float* Wxi_w   = (const float*)d_in[6];
    const float* Wxi_b   = (const float*)d_in[7];
    const float* Whf     = (const float*)d_in[8];
    const float* Wxf_w   = (const float*)d_in[9];
    const float* Wxf_b   = (const float*)d_in[10];
    const float* Whi2    = (const float*)d_in[11];
    const float* Wxi2_w  = (const float*)d_in[12];
    const float* Wxi2_b  = (const float*)d_in[13];
    const float* Whf2    = (const float*)d_in[14];
    const float* Wxf2_w  = (const float*)d_in[15];
    const float* Wxf2_b  = (const float*)d_in[16];
    float* out = (float*)d_out;

    float *embeds, *embeds_tf, *xi1, *xf1, *xi2, *xf2;
    float *lats1, *lats1_tf, *lats2, *lats2_tf, *p0, *p1, *h2o_tf, *wx_tf;
    cudaGetSymbolAddress((void**)&embeds, g_embeds);
    cudaGetSymbolAddress((void**)&embeds_tf, g_embeds_tf);
    cudaGetSymbolAddress((void**)&xi1, g_xi1);
    cudaGetSymbolAddress((void**)&xf1, g_xf1);
    cudaGetSymbolAddress((void**)&xi2, g_xi2);
    cudaGetSymbolAddress((void**)&xf2, g_xf2);
    cudaGetSymbolAddress((void**)&lats1, g_lats1);
    cudaGetSymbolAddress((void**)&lats1_tf, g_lats1_tf);
    cudaGetSymbolAddress((void**)&lats2, g_lats2);
    cudaGetSymbolAddress((void**)&lats2_tf, g_lats2_tf);
    cudaGetSymbolAddress((void**)&p0, g_part0);
    cudaGetSymbolAddress((void**)&p1, g_part1);
    cudaGetSymbolAddress((void**)&h2o_tf, g_h2o_tf);
    cudaGetSymbolAddress((void**)&wx_tf, g_wx_tf);

    const int SMEM_REC = 2 * 32 * 128 * 4 + 32 * 33 * 16;   // 49664 bytes
    static bool attr_done = false;
    if (!attr_done) {
        cudaFuncSetAttribute(ran_recurrence,
                             cudaFuncAttributeMaxDynamicSharedMemorySize, SMEM_REC);
        cudaFuncSetAttribute(gemm_tf32_pipe,
                             cudaFuncAttributeMaxDynamicSharedMemorySize, GEMM_SMEM);
        attr_done = true;
    }

    // output layout (reference return order): latent | logits | ig_last | fg_last
    float* out_latent = out;
    float* out_logits = out + BH;
    float* out_ig     = out + (size_t)BH + (size_t)SB * VOCAB;
    float* out_fg     = out_ig + BH;

    float* wxi_tf  = wx_tf;
    float* wxf_tf  = wx_tf + (size_t)HID * EMB;
    float* wxi2_tf = wx_tf + 2 * (size_t)HID * EMB;
    float* wxf2_tf = wx_tf + 3 * (size_t)HID * EMB;

    // 0) tf32 pre-rounding of GEMM weights
    {
        int n4w = (int)((size_t)VOCAB * HID / 4);
        to_tf32_kernel<<<(n4w + 255) / 256, 256>>>(h2o_w, h2o_tf, n4w);
        int n4 = HID * EMB / 4;
        to_tf32_kernel<<<(n4 + 255) / 256, 256>>>(Wxi_w, wxi_tf, n4);
        to_tf32_kernel<<<(n4 + 255) / 256, 256>>>(Wxf_w, wxf_tf, n4);
        to_tf32_kernel<<<(n4 + 255) / 256, 256>>>(Wxi2_w, wxi2_tf, n4);
        to_tf32_kernel<<<(n4 + 255) / 256, 256>>>(Wxf2_w, wxf2_tf, n4);
    }

    // 1) embedding gather (fp32 + tf32 copies)
    embed_gather<<<SB, 256>>>(word, emb, embeds, embeds_tf);

    // 2) layer-1 input gate pre-activations
    {
        dim3 grid(HID / 128, SB / 128);
        gemm_tf32_pipe<<<grid, 256, GEMM_SMEM>>>(embeds_tf, wxi_tf, Wxi_b, xi1, SB, HID, EMB);
        gemm_tf32_pipe<<<grid, 256, GEMM_SMEM>>>(embeds_tf, wxf_tf, Wxf_b, xf1, SB, HID, EMB);
    }

    // 3) layer-1 recurrence (persistent, exact fp32)
    ran_recurrence<<<NBLK, 256, SMEM_REC>>>(Whi, Whf, xi1, xf1, embeds, latent0,
                                            lats1, lats1_tf, p0, p1, nullptr, nullptr);

    // 4) layer-2 input gate pre-activations (input = l1_out)
    {
        dim3 grid(HID / 128, SB / 128);
        gemm_tf32_pipe<<<grid, 256, GEMM_SMEM>>>(lats1_tf, wxi2_tf, Wxi2_b, xi2, SB, HID, EMB);
        gemm_tf32_pipe<<<grid, 256, GEMM_SMEM>>>(lats1_tf, wxf2_tf, Wxf2_b, xf2, SB, HID, EMB);
    }

    // 5) layer-2 recurrence (initial latent = layer-1 final latent)
    ran_recurrence<<<NBLK, 256, SMEM_REC>>>(Whi2, Whf2, xi2, xf2, lats1,
                                            lats1 + (size_t)(S_LEN - 1) * BH,
                                            lats2, lats2_tf, p0, p1, out_ig, out_fg);

    // 6) final latent copy
    cudaMemcpyAsync(out_latent, lats2 + (size_t)(S_LEN - 1) * BH,
                    BH * sizeof(float), cudaMemcpyDeviceToDevice);

    // 7) logits = l2_out @ h2o_w^T + h2o_b
    {
        dim3 grid(VOCAB / 128, SB / 128);
        gemm_tf32_pipe<<<grid, 256, GEMM_SMEM>>>(lats2_tf, h2o_tf, h2o_b, out_logits,
                                                 SB, VOCAB, HID);
    }

    (void)in_sizes; (void)n_in; (void)out_size;
}